// round 16
// baseline (speedup 1.0000x reference)
#include <cuda_runtime.h>
#include <math.h>

// ---------------------------------------------------------------------------
// KAN recommender, round 16 plan:
//   prep_kernel   : coalesced-read fold of layer0 weights into DUPLICATED
//                   (pre-splatted) layout Wt0d[(i*9+j)*128 + o2*4] = {w_e,w_e,w_o,w_o}
//                   + builds layer1 spline table (knots/recips/folded coefs)
//   layer0_kernel : phase A features in smem; phase B packed fma.rn.f32x2
//   final_kernel  : table-driven layer1 (no RCPs), reduce, sigmoid
// ---------------------------------------------------------------------------

#define NBATCH 1024
#define IN0    128
#define OUT0   64
#define JF     9
#define ITILES 4
#define ICHUNK 32
#define BROWS  32

__device__ float d_Wt0d[IN0 * JF * 128];          // 147456 floats (dup layout)
__device__ float d_part[ITILES * NBATCH * OUT0];  // partial layer0 sums
__device__ float d_L1tab[OUT0 * 53];              // layer1: 12 kn,30 rc,8 fc,1 sb

#define FMA2(acc, a, b) \
    asm("fma.rn.f32x2 %0, %1, %2, %0;" : "+l"(acc) : "l"(a), "l"(b))
#define UNPACK2(lo, hi, v) \
    asm("mov.b64 {%0, %1}, %2;" : "=f"(lo), "=f"(hi) : "l"(v))

// ---------------------------------------------------------------------------
// prep: T<65536 -> coef fold (coalesced reads, scattered float2 dup stores)
//       65536<=T<73728 -> sb0 fold (j=8)
//       73728<=T<73792 -> layer1 table (o = T-73728)
// ---------------------------------------------------------------------------
__global__ void prep_kernel(const float* __restrict__ coef0,
                            const float* __restrict__ sb0,
                            const float* __restrict__ ssp0,
                            const float* __restrict__ grid1,
                            const float* __restrict__ coef1,
                            const float* __restrict__ sb1,
                            const float* __restrict__ ssp1) {
    int T = blockIdx.x * blockDim.x + threadIdx.x;
    if (T < 65536) {                       // coef path: n = T>>3, j = T&7
        int n = T >> 3, j = T & 7;
        float v = ssp0[n] * coef0[T];
        int o = n >> 7, i = n & 127;
        int dst = (i * JF + j) * 128 + (o >> 1) * 4 + (o & 1) * 2;
        *(float2*)&d_Wt0d[dst] = make_float2(v, v);
    } else if (T < 73728) {                // sb path: j = 8
        int n = T - 65536;
        float v = sb0[n];
        int o = n >> 7, i = n & 127;
        int dst = (i * JF + 8) * 128 + (o >> 1) * 4 + (o & 1) * 2;
        *(float2*)&d_Wt0d[dst] = make_float2(v, v);
    } else if (T < 73728 + OUT0) {         // layer1 table
        int o = T - 73728;
        float g[6];
        #pragma unroll
        for (int m = 0; m < 6; m++) g[m] = grid1[o * 6 + m];
        float h = (g[5] - g[0]) * 0.2f;
        float kn[12];
        kn[0] = g[0] - 3.f * h; kn[1] = g[0] - 2.f * h; kn[2] = g[0] - h;
        #pragma unroll
        for (int m = 0; m < 6; m++) kn[3 + m] = g[m];
        kn[9] = g[5] + h; kn[10] = g[5] + 2.f * h; kn[11] = g[5] + 3.f * h;
        float* tb = d_L1tab + o * 53;
        #pragma unroll
        for (int m = 0; m < 12; m++) tb[m] = kn[m];
        #pragma unroll
        for (int a = 0; a < 11; a++) tb[12 + a] = 1.0f / (kn[a + 1] - kn[a]);
        #pragma unroll
        for (int a = 0; a < 10; a++) tb[23 + a] = 1.0f / (kn[a + 2] - kn[a]);
        #pragma unroll
        for (int a = 0; a < 9;  a++) tb[33 + a] = 1.0f / (kn[a + 3] - kn[a]);
        float ss = ssp1[o];
        #pragma unroll
        for (int j = 0; j < 8; j++) tb[42 + j] = ss * coef1[o * 8 + j];
        tb[50] = sb1[o];
    }
}

// ---------------------------------------------------------------------------
// Layer0.  blockIdx.x = i-tile (0..3), blockIdx.y = b-tile (0..31), 256 thr.
// ---------------------------------------------------------------------------
__global__ void __launch_bounds__(256) layer0_kernel(
        const int*   __restrict__ uidx,
        const int*   __restrict__ iidx,
        const float* __restrict__ emb_u,
        const float* __restrict__ emb_i,
        const float* __restrict__ grid0) {

    __shared__ float s_kn[ICHUNK][13];
    __shared__ float s_rec[ICHUNK][33];
    __shared__ __align__(16) float s_feat[ICHUNK * JF * BROWS];

    int tid   = threadIdx.x;
    int itile = blockIdx.x;
    int btile = blockIdx.y;

    // ---- per-i knot extension + reciprocal denominators (1 warp) ----------
    if (tid < ICHUNK) {
        int ig = itile * ICHUNK + tid;
        float g[6];
        #pragma unroll
        for (int m = 0; m < 6; m++) g[m] = grid0[ig * 6 + m];
        float h = (g[5] - g[0]) * 0.2f;
        float kn[12];
        kn[0] = g[0] - 3.f * h; kn[1] = g[0] - 2.f * h; kn[2] = g[0] - h;
        #pragma unroll
        for (int m = 0; m < 6; m++) kn[3 + m] = g[m];
        kn[9] = g[5] + h; kn[10] = g[5] + 2.f * h; kn[11] = g[5] + 3.f * h;
        #pragma unroll
        for (int m = 0; m < 12; m++) s_kn[tid][m] = kn[m];
        int off = 0;
        #pragma unroll
        for (int kk = 1; kk <= 3; kk++) {
            for (int a = 0; a <= 11 - kk; a++)
                s_rec[tid][off + a] = 1.0f / (kn[a + kk] - kn[a]);
            off += 12 - kk;
        }
    }
    __syncthreads();

    // ---- phase A: features for 32 rows x 32 inputs ------------------------
    for (int p = tid; p < BROWS * ICHUNK; p += 256) {
        int il = p & (ICHUNK - 1);
        int r  = p >> 5;
        int b  = btile * BROWS + r;
        int ig = itile * ICHUNK + il;
        float x;
        if (ig < 64) x = emb_u[(long)uidx[b] * 64 + ig];
        else         x = emb_i[(long)iidx[b] * 64 + (ig - 64)];
        float sl = x / (1.0f + __expf(-x));   // silu

        const float* kn = s_kn[il];
        const float* rc = s_rec[il];
        float Bv[11];
        #pragma unroll
        for (int m = 0; m < 11; m++)
            Bv[m] = (x >= kn[m] && x < kn[m + 1]) ? 1.0f : 0.0f;
        #pragma unroll
        for (int m = 0; m < 10; m++)
            Bv[m] = (x - kn[m]) * rc[m] * Bv[m]
                  + (kn[m + 2] - x) * rc[m + 1] * Bv[m + 1];
        #pragma unroll
        for (int m = 0; m < 9; m++)
            Bv[m] = (x - kn[m]) * rc[11 + m] * Bv[m]
                  + (kn[m + 3] - x) * rc[11 + m + 1] * Bv[m + 1];
        #pragma unroll
        for (int m = 0; m < 8; m++)
            Bv[m] = (x - kn[m]) * rc[21 + m] * Bv[m]
                  + (kn[m + 4] - x) * rc[21 + m + 1] * Bv[m + 1];

        #pragma unroll
        for (int j = 0; j < 8; j++)
            s_feat[(il * JF + j) * BROWS + r] = Bv[j];
        s_feat[(il * JF + 8) * BROWS + r] = sl;
    }
    __syncthreads();

    // ---- phase B: packed-fma contraction, 4 rows x 2 outs per thread ------
    int o2 = tid & 31;          // output pair (2*o2, 2*o2+1)
    int rg = tid >> 5;          // 4-row group (== warp id -> broadcast LDS)

    unsigned long long a01x = 0ULL, a23x = 0ULL, a01y = 0ULL, a23y = 0ULL;

    const float* wbase = d_Wt0d + (itile * ICHUNK) * JF * 128 + o2 * 4;

    #pragma unroll 1
    for (int il = 0; il < ICHUNK; il++) {
        #pragma unroll
        for (int j = 0; j < JF; j++) {
            int k = il * JF + j;
            ulonglong2 fv = *(const ulonglong2*)&s_feat[k * BROWS + rg * 4];
            ulonglong2 wv = *(const ulonglong2*)&wbase[k * 128];
            FMA2(a01x, fv.x, wv.x);   // rows 0,1 x even-o
            FMA2(a23x, fv.y, wv.x);   // rows 2,3 x even-o
            FMA2(a01y, fv.x, wv.y);   // rows 0,1 x odd-o
            FMA2(a23y, fv.y, wv.y);   // rows 2,3 x odd-o
        }
    }

    float r0x, r1x, r2x, r3x, r0y, r1y, r2y, r3y;
    UNPACK2(r0x, r1x, a01x); UNPACK2(r2x, r3x, a23x);
    UNPACK2(r0y, r1y, a01y); UNPACK2(r2y, r3y, a23y);

    int b0 = btile * BROWS + rg * 4;
    float2* pp = (float2*)&d_part[((long)itile * NBATCH + b0) * OUT0 + o2 * 2];
    pp[0 * (OUT0 / 2)] = make_float2(r0x, r0y);
    pp[1 * (OUT0 / 2)] = make_float2(r1x, r1y);
    pp[2 * (OUT0 / 2)] = make_float2(r2x, r2y);
    pp[3 * (OUT0 / 2)] = make_float2(r3x, r3y);
}

// ---------------------------------------------------------------------------
// Final: reduce i-tiles + bias0, table-driven layer1 (no RCPs), reduce 64,
// bias1 + sigmoid.  4 batch rows per CTA (256 threads).
// ---------------------------------------------------------------------------
__global__ void __launch_bounds__(256) final_kernel(
        const float* __restrict__ bias0,
        const float* __restrict__ bias1,
        float* __restrict__ out) {

    __shared__ float s_tab[OUT0 * 53];
    __shared__ float red[8];

    int tid = threadIdx.x;
    for (int idx = tid; idx < OUT0 * 53; idx += 256)
        s_tab[idx] = d_L1tab[idx];

    int o  = tid & 63;
    int bs = tid >> 6;
    int b  = blockIdx.x * 4 + bs;

    float x = bias0[o];
    #pragma unroll
    for (int t = 0; t < ITILES; t++)
        x += d_part[((long)t * NBATCH + b) * OUT0 + o];
    __syncthreads();

    const float* tb = &s_tab[o * 53];
    float Bv[11];
    #pragma unroll
    for (int m = 0; m < 11; m++)
        Bv[m] = (x >= tb[m] && x < tb[m + 1]) ? 1.0f : 0.0f;
    #pragma unroll
    for (int m = 0; m < 10; m++)
        Bv[m] = (x - tb[m]) * tb[12 + m] * Bv[m]
              + (tb[m + 2] - x) * tb[12 + m + 1] * Bv[m + 1];
    #pragma unroll
    for (int m = 0; m < 9; m++)
        Bv[m] = (x - tb[m]) * tb[23 + m] * Bv[m]
              + (tb[m + 3] - x) * tb[23 + m + 1] * Bv[m + 1];
    #pragma unroll
    for (int m = 0; m < 8; m++)
        Bv[m] = (x - tb[m]) * tb[33 + m] * Bv[m]
              + (tb[m + 4] - x) * tb[33 + m + 1] * Bv[m + 1];

    float sl  = x / (1.0f + __expf(-x));
    float dot = 0.f;
    #pragma unroll
    for (int j = 0; j < 8; j++) dot += tb[42 + j] * Bv[j];
    float c = tb[50] * sl + dot;

    #pragma unroll
    for (int s = 16; s > 0; s >>= 1)
        c += __shfl_down_sync(0xffffffffu, c, s);
    int warp = tid >> 5;
    if ((tid & 31) == 0) red[warp] = c;
    __syncthreads();
    if (tid < 4) {
        float z = red[2 * tid] + red[2 * tid + 1] + bias1[0];
        out[blockIdx.x * 4 + tid] = 1.0f / (1.0f + __expf(-z));
    }
}

// ---------------------------------------------------------------------------
extern "C" void kernel_launch(void* const* d_in, const int* in_sizes, int n_in,
                              void* d_out, int out_size) {
    const int*   uidx  = (const int*)  d_in[0];
    const int*   iidx  = (const int*)  d_in[1];
    // d_in[2], d_in[3]: grid_update_num / stop_grid_update_step (unused)
    const float* emb_u = (const float*)d_in[4];
    const float* emb_i = (const float*)d_in[5];
    const float* grid0 = (const float*)d_in[6];
    const float* coef0 = (const float*)d_in[7];
    const float* sb0   = (const float*)d_in[8];
    const float* ssp0  = (const float*)d_in[9];
    const float* bias0 = (const float*)d_in[10];
    const float* grid1 = (const float*)d_in[11];
    const float* coef1 = (const float*)d_in[12];
    const float* sb1   = (const float*)d_in[13];
    const float* ssp1  = (const float*)d_in[14];
    const float* bias1 = (const float*)d_in[15];
    float* out = (float*)d_out;

    prep_kernel<<<(73728 + OUT0 + 255) / 256, 256>>>(coef0, sb0, ssp0,
                                                     grid1, coef1, sb1, ssp1);

    dim3 g1(ITILES, NBATCH / BROWS);   // (4, 32)
    layer0_kernel<<<g1, 256>>>(uidx, iidx, emb_u, emb_i, grid0);

    final_kernel<<<NBATCH / 4, 256>>>(bias0, bias1, out);
}

// round 17
// speedup vs baseline: 1.1319x; 1.1319x over previous
#include <cuda_runtime.h>
#include <math.h>

// ---------------------------------------------------------------------------
// R17 = R15 (best: 31.5us) + table-driven final_kernel (kills the ~2M fp32
// divides that R15's final executed). prep/layer0 identical to R15.
// ---------------------------------------------------------------------------

#define NBATCH 1024
#define IN0    128
#define OUT0   64
#define JF     9
#define ITILES 4
#define ICHUNK 32
#define BROWS  32

__device__ float d_Wt0[IN0 * JF * OUT0];          // folded weights (R15 layout)
__device__ float d_part[ITILES * NBATCH * OUT0];  // partial layer0 sums
__device__ float d_L1tab[OUT0 * 53];              // layer1: 12 kn,30 rc,8 fc,1 sb

// ---------------------------------------------------------------------------
// prep: idx<73728 -> R15 weight fold; 73728<=idx<73792 -> layer1 table.
// ---------------------------------------------------------------------------
__global__ void prep_kernel(const float* __restrict__ coef0,
                            const float* __restrict__ sb0,
                            const float* __restrict__ ssp0,
                            const float* __restrict__ grid1,
                            const float* __restrict__ coef1,
                            const float* __restrict__ sb1,
                            const float* __restrict__ ssp1) {
    int idx = blockIdx.x * blockDim.x + threadIdx.x;
    if (idx < IN0 * JF * OUT0) {
        int o  = idx & (OUT0 - 1);
        int ij = idx >> 6;
        int j  = ij % JF;
        int i  = ij / JF;
        int n  = o * IN0 + i;
        d_Wt0[idx] = (j < 8) ? ssp0[n] * coef0[n * 8 + j] : sb0[n];
    } else if (idx < IN0 * JF * OUT0 + OUT0) {
        int o = idx - IN0 * JF * OUT0;
        float g[6];
        #pragma unroll
        for (int m = 0; m < 6; m++) g[m] = grid1[o * 6 + m];
        float h = (g[5] - g[0]) * 0.2f;
        float kn[12];
        kn[0] = g[0] - 3.f * h; kn[1] = g[0] - 2.f * h; kn[2] = g[0] - h;
        #pragma unroll
        for (int m = 0; m < 6; m++) kn[3 + m] = g[m];
        kn[9] = g[5] + h; kn[10] = g[5] + 2.f * h; kn[11] = g[5] + 3.f * h;
        float* tb = d_L1tab + o * 53;
        #pragma unroll
        for (int m = 0; m < 12; m++) tb[m] = kn[m];
        #pragma unroll
        for (int a = 0; a < 11; a++) tb[12 + a] = 1.0f / (kn[a + 1] - kn[a]);
        #pragma unroll
        for (int a = 0; a < 10; a++) tb[23 + a] = 1.0f / (kn[a + 2] - kn[a]);
        #pragma unroll
        for (int a = 0; a < 9;  a++) tb[33 + a] = 1.0f / (kn[a + 3] - kn[a]);
        float ss = ssp1[o];
        #pragma unroll
        for (int j = 0; j < 8; j++) tb[42 + j] = ss * coef1[o * 8 + j];
        tb[50] = sb1[o];
    }
}

// ---------------------------------------------------------------------------
// Layer0 (identical to R15).  grid (4 i-tiles x 32 b-tiles), 256 threads.
// ---------------------------------------------------------------------------
__global__ void __launch_bounds__(256) layer0_kernel(
        const int*   __restrict__ uidx,
        const int*   __restrict__ iidx,
        const float* __restrict__ emb_u,
        const float* __restrict__ emb_i,
        const float* __restrict__ grid0) {

    __shared__ float s_kn[ICHUNK][13];
    __shared__ float s_rec[ICHUNK][33];
    __shared__ __align__(16) float s_feat[ICHUNK * JF * BROWS];

    int tid   = threadIdx.x;
    int itile = blockIdx.x;
    int btile = blockIdx.y;

    if (tid < ICHUNK) {
        int ig = itile * ICHUNK + tid;
        float g[6];
        #pragma unroll
        for (int m = 0; m < 6; m++) g[m] = grid0[ig * 6 + m];
        float h = (g[5] - g[0]) * 0.2f;
        float kn[12];
        kn[0] = g[0] - 3.f * h; kn[1] = g[0] - 2.f * h; kn[2] = g[0] - h;
        #pragma unroll
        for (int m = 0; m < 6; m++) kn[3 + m] = g[m];
        kn[9] = g[5] + h; kn[10] = g[5] + 2.f * h; kn[11] = g[5] + 3.f * h;
        #pragma unroll
        for (int m = 0; m < 12; m++) s_kn[tid][m] = kn[m];
        int off = 0;
        #pragma unroll
        for (int kk = 1; kk <= 3; kk++) {
            for (int a = 0; a <= 11 - kk; a++)
                s_rec[tid][off + a] = 1.0f / (kn[a + kk] - kn[a]);
            off += 12 - kk;
        }
    }
    __syncthreads();

    for (int p = tid; p < BROWS * ICHUNK; p += 256) {
        int il = p & (ICHUNK - 1);
        int r  = p >> 5;
        int b  = btile * BROWS + r;
        int ig = itile * ICHUNK + il;
        float x;
        if (ig < 64) x = emb_u[(long)uidx[b] * 64 + ig];
        else         x = emb_i[(long)iidx[b] * 64 + (ig - 64)];
        float sl = x / (1.0f + __expf(-x));   // silu

        const float* kn = s_kn[il];
        const float* rc = s_rec[il];
        float Bv[11];
        #pragma unroll
        for (int m = 0; m < 11; m++)
            Bv[m] = (x >= kn[m] && x < kn[m + 1]) ? 1.0f : 0.0f;
        #pragma unroll
        for (int m = 0; m < 10; m++)
            Bv[m] = (x - kn[m]) * rc[m] * Bv[m]
                  + (kn[m + 2] - x) * rc[m + 1] * Bv[m + 1];
        #pragma unroll
        for (int m = 0; m < 9; m++)
            Bv[m] = (x - kn[m]) * rc[11 + m] * Bv[m]
                  + (kn[m + 3] - x) * rc[11 + m + 1] * Bv[m + 1];
        #pragma unroll
        for (int m = 0; m < 8; m++)
            Bv[m] = (x - kn[m]) * rc[21 + m] * Bv[m]
                  + (kn[m + 4] - x) * rc[21 + m + 1] * Bv[m + 1];

        #pragma unroll
        for (int j = 0; j < 8; j++)
            s_feat[(il * JF + j) * BROWS + r] = Bv[j];
        s_feat[(il * JF + 8) * BROWS + r] = sl;
    }
    __syncthreads();

    int o2 = tid & 31;
    int rg = tid >> 5;
    float2 acc0 = {0.f, 0.f}, acc1 = {0.f, 0.f}, acc2 = {0.f, 0.f}, acc3 = {0.f, 0.f};

    const float* wbase = d_Wt0 + (itile * ICHUNK) * JF * OUT0 + o2 * 2;

    #pragma unroll 1
    for (int il = 0; il < ICHUNK; il++) {
        #pragma unroll
        for (int j = 0; j < JF; j++) {
            float4 f = *(const float4*)&s_feat[(il * JF + j) * BROWS + rg * 4];
            float2 w = *(const float2*)&wbase[(il * JF + j) * OUT0];
            acc0.x += f.x * w.x; acc0.y += f.x * w.y;
            acc1.x += f.y * w.x; acc1.y += f.y * w.y;
            acc2.x += f.z * w.x; acc2.y += f.z * w.y;
            acc3.x += f.w * w.x; acc3.y += f.w * w.y;
        }
    }

    int b0 = btile * BROWS + rg * 4;
    float2* pp = (float2*)&d_part[((long)itile * NBATCH + b0) * OUT0 + o2 * 2];
    pp[0 * (OUT0 / 2)] = acc0;
    pp[1 * (OUT0 / 2)] = acc1;
    pp[2 * (OUT0 / 2)] = acc2;
    pp[3 * (OUT0 / 2)] = acc3;
}

// ---------------------------------------------------------------------------
// Final: table-driven layer1 (ZERO divides), reduce 64, bias1 + sigmoid.
// 4 batch rows per CTA (256 threads).
// ---------------------------------------------------------------------------
__global__ void __launch_bounds__(256) final_kernel(
        const float* __restrict__ bias0,
        const float* __restrict__ bias1,
        float* __restrict__ out) {

    __shared__ float s_tab[OUT0 * 53];
    __shared__ float red[8];

    int tid = threadIdx.x;
    for (int idx = tid; idx < OUT0 * 53; idx += 256)
        s_tab[idx] = d_L1tab[idx];

    int o  = tid & 63;
    int bs = tid >> 6;
    int b  = blockIdx.x * 4 + bs;

    float x = bias0[o];
    #pragma unroll
    for (int t = 0; t < ITILES; t++)
        x += d_part[((long)t * NBATCH + b) * OUT0 + o];
    __syncthreads();

    const float* tb = &s_tab[o * 53];
    float Bv[11];
    #pragma unroll
    for (int m = 0; m < 11; m++)
        Bv[m] = (x >= tb[m] && x < tb[m + 1]) ? 1.0f : 0.0f;
    #pragma unroll
    for (int m = 0; m < 10; m++)
        Bv[m] = (x - tb[m]) * tb[12 + m] * Bv[m]
              + (tb[m + 2] - x) * tb[12 + m + 1] * Bv[m + 1];
    #pragma unroll
    for (int m = 0; m < 9; m++)
        Bv[m] = (x - tb[m]) * tb[23 + m] * Bv[m]
              + (tb[m + 3] - x) * tb[23 + m + 1] * Bv[m + 1];
    #pragma unroll
    for (int m = 0; m < 8; m++)
        Bv[m] = (x - tb[m]) * tb[33 + m] * Bv[m]
              + (tb[m + 4] - x) * tb[33 + m + 1] * Bv[m + 1];

    float sl  = x / (1.0f + __expf(-x));
    float dot = 0.f;
    #pragma unroll
    for (int j = 0; j < 8; j++) dot += tb[42 + j] * Bv[j];
    float c = tb[50] * sl + dot;

    #pragma unroll
    for (int s = 16; s > 0; s >>= 1)
        c += __shfl_down_sync(0xffffffffu, c, s);
    int warp = tid >> 5;
    if ((tid & 31) == 0) red[warp] = c;
    __syncthreads();
    if (tid < 4) {
        float z = red[2 * tid] + red[2 * tid + 1] + bias1[0];
        out[blockIdx.x * 4 + tid] = 1.0f / (1.0f + __expf(-z));
    }
}

// ---------------------------------------------------------------------------
extern "C" void kernel_launch(void* const* d_in, const int* in_sizes, int n_in,
                              void* d_out, int out_size) {
    const int*   uidx  = (const int*)  d_in[0];
    const int*   iidx  = (const int*)  d_in[1];
    // d_in[2], d_in[3]: grid_update_num / stop_grid_update_step (unused)
    const float* emb_u = (const float*)d_in[4];
    const float* emb_i = (const float*)d_in[5];
    const float* grid0 = (const float*)d_in[6];
    const float* coef0 = (const float*)d_in[7];
    const float* sb0   = (const float*)d_in[8];
    const float* ssp0  = (const float*)d_in[9];
    const float* bias0 = (const float*)d_in[10];
    const float* grid1 = (const float*)d_in[11];
    const float* coef1 = (const float*)d_in[12];
    const float* sb1   = (const float*)d_in[13];
    const float* ssp1  = (const float*)d_in[14];
    const float* bias1 = (const float*)d_in[15];
    float* out = (float*)d_out;

    prep_kernel<<<(IN0 * JF * OUT0 + OUT0 + 255) / 256, 256>>>(
        coef0, sb0, ssp0, grid1, coef1, sb1, ssp1);

    dim3 g1(ITILES, NBATCH / BROWS);   // (4, 32)
    layer0_kernel<<<g1, 256>>>(uidx, iidx, emb_u, emb_i, grid0);

    final_kernel<<<NBATCH / 4, 256>>>(bias0, bias1, out);
}